// round 1
// baseline (speedup 1.0000x reference)
#include <cuda_runtime.h>
#include <math.h>

// ---------------- problem constants ----------------
#define PB   16
#define PS   512
#define PD   512
#define PH   8
#define PDK  64
#define PF   2048
#define PM   (PB*PS)          // 8192 rows
#define LN_EPS 1e-5f

// ---------------- scratch (device globals; no allocation) ----------------
__device__ float g_q[(size_t)PM * PD];
__device__ float g_v[(size_t)PM * PD];
__device__ float g_o[(size_t)PM * PD];
__device__ float g_a[(size_t)PM * PD];
__device__ float g_t[(size_t)PM * PD];   // y1 / x2 (pre-FFN residual)
__device__ float g_y[(size_t)PM * PD];   // block0 output
__device__ float g_x[(size_t)PM * PD];   // block1 output
__device__ float g_h[(size_t)PM * PF];   // FFN hidden

// ---------------- warp utils ----------------
__device__ __forceinline__ float warpMax(float v) {
#pragma unroll
    for (int o = 16; o; o >>= 1) v = fmaxf(v, __shfl_xor_sync(0xffffffffu, v, o));
    return v;
}
__device__ __forceinline__ float warpSum(float v) {
#pragma unroll
    for (int o = 16; o; o >>= 1) v += __shfl_xor_sync(0xffffffffu, v, o);
    return v;
}

// ---------------- SGEMM: C[M,N] = A[M,K] @ W[K,N] + bias, optional ReLU ----------------
// BM=BN=64, BK=16, 256 threads, 4x4 micro-tile. M%64==0, N%64==0, K%16==0 assumed.
template <int RELU>
__global__ __launch_bounds__(256) void sgemm_kernel(
    const float* __restrict__ A, const float* __restrict__ W,
    const float* __restrict__ bias, float* __restrict__ C,
    int Mv, int Nv, int Kv)
{
    __shared__ float sA[16][68];   // [k][m], padded
    __shared__ float sB[16][64];   // [k][n]
    const int bx = blockIdx.x * 64;
    const int by = blockIdx.y * 64;
    const int tid = threadIdx.x;
    const int tx = tid & 15;   // n-group
    const int ty = tid >> 4;   // m-group
    float acc[4][4] = {};

    for (int k0 = 0; k0 < Kv; k0 += 16) {
#pragma unroll
        for (int i = 0; i < 4; i++) {
            int idx = tid + i * 256;
            int r = idx >> 4, c = idx & 15;
            sA[c][r] = A[(size_t)(by + r) * Kv + k0 + c];
        }
#pragma unroll
        for (int i = 0; i < 4; i++) {
            int idx = tid + i * 256;
            int kk = idx >> 6, n = idx & 63;
            sB[kk][n] = W[(size_t)(k0 + kk) * Nv + bx + n];
        }
        __syncthreads();
#pragma unroll
        for (int k = 0; k < 16; k++) {
            float4 a4 = *(const float4*)&sA[k][ty * 4];
            float4 b4 = *(const float4*)&sB[k][tx * 4];
            acc[0][0] += a4.x * b4.x; acc[0][1] += a4.x * b4.y;
            acc[0][2] += a4.x * b4.z; acc[0][3] += a4.x * b4.w;
            acc[1][0] += a4.y * b4.x; acc[1][1] += a4.y * b4.y;
            acc[1][2] += a4.y * b4.z; acc[1][3] += a4.y * b4.w;
            acc[2][0] += a4.z * b4.x; acc[2][1] += a4.z * b4.y;
            acc[2][2] += a4.z * b4.z; acc[2][3] += a4.z * b4.w;
            acc[3][0] += a4.w * b4.x; acc[3][1] += a4.w * b4.y;
            acc[3][2] += a4.w * b4.z; acc[3][3] += a4.w * b4.w;
        }
        __syncthreads();
    }

    const float bz0 = bias[bx + tx * 4 + 0];
    const float bz1 = bias[bx + tx * 4 + 1];
    const float bz2 = bias[bx + tx * 4 + 2];
    const float bz3 = bias[bx + tx * 4 + 3];
#pragma unroll
    for (int ii = 0; ii < 4; ii++) {
        float r0 = acc[ii][0] + bz0;
        float r1 = acc[ii][1] + bz1;
        float r2 = acc[ii][2] + bz2;
        float r3 = acc[ii][3] + bz3;
        if (RELU) {
            r0 = fmaxf(r0, 0.f); r1 = fmaxf(r1, 0.f);
            r2 = fmaxf(r2, 0.f); r3 = fmaxf(r3, 0.f);
        }
        *(float4*)&C[(size_t)(by + ty * 4 + ii) * Nv + bx + tx * 4] =
            make_float4(r0, r1, r2, r3);
    }
}

// ---------------- fused add + LayerNorm: out = LN(a + b) * g + beta ----------------
__global__ __launch_bounds__(128) void add_ln_kernel(
    const float* __restrict__ A, const float* __restrict__ Bv,
    const float* __restrict__ g, const float* __restrict__ be,
    float* __restrict__ out)
{
    __shared__ float red[16];
    const int row = blockIdx.x;
    const int tid = threadIdx.x;           // 128 threads, 4 floats each
    const int lane = tid & 31, wid = tid >> 5;
    float4 xa = ((const float4*)(A  + (size_t)row * PD))[tid];
    float4 xb = ((const float4*)(Bv + (size_t)row * PD))[tid];
    float x0 = xa.x + xb.x, x1 = xa.y + xb.y, x2 = xa.z + xb.z, x3 = xa.w + xb.w;

    float s = warpSum(x0 + x1 + x2 + x3);
    if (lane == 0) red[wid] = s;
    __syncthreads();
    float mean = (red[0] + red[1] + red[2] + red[3]) * (1.0f / PD);

    float d0 = x0 - mean, d1 = x1 - mean, d2 = x2 - mean, d3 = x3 - mean;
    float vs = warpSum(d0 * d0 + d1 * d1 + d2 * d2 + d3 * d3);
    if (lane == 0) red[8 + wid] = vs;
    __syncthreads();
    float var = (red[8] + red[9] + red[10] + red[11]) * (1.0f / PD);
    float rstd = rsqrtf(var + LN_EPS);

    float4 gg = ((const float4*)g)[tid];
    float4 bb = ((const float4*)be)[tid];
    float4 o;
    o.x = d0 * rstd * gg.x + bb.x;
    o.y = d1 * rstd * gg.y + bb.y;
    o.z = d2 * rstd * gg.z + bb.z;
    o.w = d3 * rstd * gg.w + bb.w;
    ((float4*)(out + (size_t)row * PD))[tid] = o;
}

// ---------------- fused distance-decay attention ----------------
// Block: one (b,h), 32 query rows. Scores held in smem; two softmax passes,
// inclusive cumsum, distance decay, then AV. K == Q (kq_same).
#define ATT_ROWS 32
#define ATT_JT   128
#define SS_LD    516
#define KV_LD    68
#define ATT_SMEM ((ATT_ROWS*64 + ATT_ROWS*SS_LD + ATT_JT*KV_LD) * 4)

__global__ __launch_bounds__(256) void attn_kernel(
    const float* __restrict__ Q, const float* __restrict__ V,
    const float* __restrict__ gammas, int layer, int strict,
    float* __restrict__ O)
{
    extern __shared__ float sm[];
    float* sQ  = sm;                               // 32 x 64
    float* sS  = sQ + ATT_ROWS * 64;               // 32 x 516 (padded)
    float* sKV = sS + ATT_ROWS * SS_LD;            // 128 x 68 (padded)

    const int bh = blockIdx.x;
    const int b = bh >> 3, h = bh & 7;
    const int i0 = blockIdx.y * ATT_ROWS;
    const int tid = threadIdx.x;
    const int lane = tid & 31, w = tid >> 5;

    float gamma = gammas[layer * PH + h];
    // -softplus(gamma), overflow-safe
    float gneg = (gamma > 20.f) ? -gamma : -log1pf(expf(gamma));

    const float* Qb = Q + (size_t)(b * PS) * PD + h * PDK;
    const float* Vb = V + (size_t)(b * PS) * PD + h * PDK;

    // load Q tile
    for (int idx = tid; idx < ATT_ROWS * PDK; idx += 256) {
        int r = idx >> 6, d = idx & 63;
        sQ[r * 64 + d] = Qb[(size_t)(i0 + r) * PD + d];
    }
    __syncthreads();

    // ---- Pass A: raw scores (all j, mask recomputed later) ----
    {
        const int ty = tid >> 5;     // 8 groups x 4 rows
        const int tx = tid & 31;     // 32 groups x 4 cols
        const int ib = ty * 4, jb = tx * 4;
        for (int j0 = 0; j0 < PS; j0 += ATT_JT) {
            for (int idx = tid; idx < ATT_JT * PDK; idx += 256) {
                int r = idx >> 6, d = idx & 63;
                sKV[r * KV_LD + d] = Qb[(size_t)(j0 + r) * PD + d];  // K == Q
            }
            __syncthreads();
            float acc[4][4] = {};
#pragma unroll 8
            for (int k = 0; k < PDK; k++) {
                float a0 = sQ[(ib + 0) * 64 + k];
                float a1 = sQ[(ib + 1) * 64 + k];
                float a2 = sQ[(ib + 2) * 64 + k];
                float a3 = sQ[(ib + 3) * 64 + k];
                float b0 = sKV[(jb + 0) * KV_LD + k];
                float b1 = sKV[(jb + 1) * KV_LD + k];
                float b2 = sKV[(jb + 2) * KV_LD + k];
                float b3 = sKV[(jb + 3) * KV_LD + k];
                acc[0][0] += a0 * b0; acc[0][1] += a0 * b1; acc[0][2] += a0 * b2; acc[0][3] += a0 * b3;
                acc[1][0] += a1 * b0; acc[1][1] += a1 * b1; acc[1][2] += a1 * b2; acc[1][3] += a1 * b3;
                acc[2][0] += a2 * b0; acc[2][1] += a2 * b1; acc[2][2] += a2 * b2; acc[2][3] += a2 * b3;
                acc[3][0] += a3 * b0; acc[3][1] += a3 * b1; acc[3][2] += a3 * b2; acc[3][3] += a3 * b3;
            }
            const float scale = 0.125f;   // 1/sqrt(64)
#pragma unroll
            for (int ii = 0; ii < 4; ii++)
#pragma unroll
                for (int jj = 0; jj < 4; jj++)
                    sS[(ib + ii) * SS_LD + j0 + jb + jj] = acc[ii][jj] * scale;
            __syncthreads();
        }
    }

    // ---- softmax1 -> cumsum -> decay -> softmax2 (warp per row) ----
    const float NEG = -1e32f;
    for (int rr = 0; rr < 4; rr++) {
        const int il = w + rr * 8;
        const int ig = i0 + il;
        float sraw[16], p[16], cum[16];
        float mx = NEG;
#pragma unroll
        for (int c = 0; c < 16; c++) {
            int j = lane + 32 * c;
            sraw[c] = sS[il * SS_LD + j];
            bool vld = strict ? (j < ig) : (j <= ig);
            float s1 = vld ? sraw[c] : NEG;
            p[c] = s1;
            mx = fmaxf(mx, s1);
        }
        mx = warpMax(mx);
        float sum = 0.f;
#pragma unroll
        for (int c = 0; c < 16; c++) { float e = expf(p[c] - mx); p[c] = e; sum += e; }
        sum = warpSum(sum);
        float inv = 1.0f / sum;
#pragma unroll
        for (int c = 0; c < 16; c++) {
            int j = lane + 32 * c;
            bool vld = strict ? (j < ig) : (j <= ig);
            p[c] = vld ? p[c] * inv : 0.f;
        }
        // inclusive cumsum along j (chunk-major: j = lane + 32*c)
        float run = 0.f;
#pragma unroll
        for (int c = 0; c < 16; c++) {
            float sc = p[c];
#pragma unroll
            for (int o = 1; o < 32; o <<= 1) {
                float t = __shfl_up_sync(0xffffffffu, sc, o);
                if (lane >= o) sc += t;
            }
            cum[c] = run + sc;
            run += __shfl_sync(0xffffffffu, sc, 31);
        }
        const float tot = run;
        float m2 = NEG;
#pragma unroll
        for (int c = 0; c < 16; c++) {
            int j = lane + 32 * c;
            bool vld = strict ? (j < ig) : (j <= ig);
            float pos = fabsf((float)(ig - j));
            float dist = sqrtf(fmaxf((tot - cum[c]) * pos, 0.f));
            float eff = expf(gneg * dist);
            eff = fminf(fmaxf(eff, 1e-5f), 1e5f);
            float v2 = vld ? sraw[c] * eff : NEG;
            p[c] = v2;
            m2 = fmaxf(m2, v2);
        }
        m2 = warpMax(m2);
        float sum2 = 0.f;
#pragma unroll
        for (int c = 0; c < 16; c++) { float e = expf(p[c] - m2); p[c] = e; sum2 += e; }
        sum2 = warpSum(sum2);
        float inv2 = 1.0f / sum2;
#pragma unroll
        for (int c = 0; c < 16; c++)
            sS[il * SS_LD + lane + 32 * c] = p[c] * inv2;
    }
    __syncthreads();

    // ---- Pass B: O = attn @ V ----
    {
        const int tx = tid & 15;    // d-group: 4 cols
        const int ty = tid >> 4;    // i-group: 2 rows
        const int ib = ty * 2, db = tx * 4;
        float acc[2][4] = {};
        for (int j0 = 0; j0 < PS; j0 += ATT_JT) {
            for (int idx = tid; idx < ATT_JT * PDK; idx += 256) {
                int r = idx >> 6, d = idx & 63;
                sKV[r * KV_LD + d] = Vb[(size_t)(j0 + r) * PD + d];
            }
            __syncthreads();
#pragma unroll 4
            for (int jj = 0; jj < ATT_JT; jj++) {
                float a0 = sS[(ib + 0) * SS_LD + j0 + jj];
                float a1 = sS[(ib + 1) * SS_LD + j0 + jj];
                float4 v4 = *(const float4*)&sKV[jj * KV_LD + db];
                acc[0][0] += a0 * v4.x; acc[0][1] += a0 * v4.y;
                acc[0][2] += a0 * v4.z; acc[0][3] += a0 * v4.w;
                acc[1][0] += a1 * v4.x; acc[1][1] += a1 * v4.y;
                acc[1][2] += a1 * v4.z; acc[1][3] += a1 * v4.w;
            }
            __syncthreads();
        }
        float* Ob = O + (size_t)(b * PS + i0) * PD + h * PDK;
#pragma unroll
        for (int ii = 0; ii < 2; ii++)
            *(float4*)&Ob[(size_t)(ib + ii) * PD + db] =
                make_float4(acc[ii][0], acc[ii][1], acc[ii][2], acc[ii][3]);
    }
}

// ---------------- host orchestration ----------------
static void run_gemm(const float* A, const float* W, const float* bias, float* C,
                     int Mv, int Nv, int Kv, bool relu, cudaStream_t st = 0)
{
    dim3 grid(Nv / 64, Mv / 64);
    if (relu) sgemm_kernel<1><<<grid, 256, 0, st>>>(A, W, bias, C, Mv, Nv, Kv);
    else      sgemm_kernel<0><<<grid, 256, 0, st>>>(A, W, bias, C, Mv, Nv, Kv);
}

extern "C" void kernel_launch(void* const* d_in, const int* in_sizes, int n_in,
                              void* d_out, int out_size)
{
    const float* q_embed  = (const float*)d_in[0];
    const float* qa_embed = (const float*)d_in[1];
    const float* Wk  = (const float*)d_in[2];
    const float* bk  = (const float*)d_in[3];
    const float* Wv  = (const float*)d_in[4];
    const float* bv  = (const float*)d_in[5];
    const float* Wo  = (const float*)d_in[6];
    const float* bo  = (const float*)d_in[7];
    const float* gam = (const float*)d_in[8];
    const float* l1g = (const float*)d_in[9];
    const float* l1b = (const float*)d_in[10];
    const float* W1  = (const float*)d_in[11];
    const float* b1  = (const float*)d_in[12];
    const float* W2  = (const float*)d_in[13];
    const float* b2  = (const float*)d_in[14];
    const float* l2g = (const float*)d_in[15];
    const float* l2b = (const float*)d_in[16];
    float* out = (float*)d_out;

    float *gq, *gv, *go, *ga, *gt, *gy, *gx, *gh;
    cudaGetSymbolAddress((void**)&gq, g_q);
    cudaGetSymbolAddress((void**)&gv, g_v);
    cudaGetSymbolAddress((void**)&go, g_o);
    cudaGetSymbolAddress((void**)&ga, g_a);
    cudaGetSymbolAddress((void**)&gt, g_t);
    cudaGetSymbolAddress((void**)&gy, g_y);
    cudaGetSymbolAddress((void**)&gx, g_x);
    cudaGetSymbolAddress((void**)&gh, g_h);

    cudaFuncSetAttribute(attn_kernel, cudaFuncAttributeMaxDynamicSharedMemorySize, ATT_SMEM);

    const size_t DD = (size_t)PD * PD, DF = (size_t)PD * PF;
    dim3 attnGrid(PB * PH, PS / ATT_ROWS);

    // ===== Block 0: knowledge encoder (input qa_embed, mask1, FFN) =====
    run_gemm(qa_embed, Wk + 0 * DD, bk + 0 * PD, gq, PM, PD, PD, false);  // q (== k)
    run_gemm(qa_embed, Wv + 0 * DD, bv + 0 * PD, gv, PM, PD, PD, false);  // v
    attn_kernel<<<attnGrid, 256, ATT_SMEM>>>(gq, gv, gam, 0, /*strict=*/0, go);
    run_gemm(go, Wo + 0 * DD, bo + 0 * PD, ga, PM, PD, PD, false);
    add_ln_kernel<<<PM, 128>>>(qa_embed, ga, l1g + 0 * PD, l1b + 0 * PD, gt);
    run_gemm(gt, W1 + 0 * DF, b1 + 0 * PF, gh, PM, PF, PD, true);         // relu
    run_gemm(gh, W2 + 0 * DF, b2 + 0 * PD, ga, PM, PD, PF, false);
    add_ln_kernel<<<PM, 128>>>(gt, ga, l2g + 0 * PD, l2b + 0 * PD, gy);   // -> y

    // ===== Block 1: question encoder (input q_embed, mask1, no FFN) =====
    run_gemm(q_embed, Wk + 1 * DD, bk + 1 * PD, gq, PM, PD, PD, false);
    run_gemm(q_embed, Wv + 1 * DD, bv + 1 * PD, gv, PM, PD, PD, false);
    attn_kernel<<<attnGrid, 256, ATT_SMEM>>>(gq, gv, gam, 1, /*strict=*/0, go);
    run_gemm(go, Wo + 1 * DD, bo + 1 * PD, ga, PM, PD, PD, false);
    add_ln_kernel<<<PM, 128>>>(q_embed, ga, l1g + 1 * PD, l1b + 1 * PD, gx);  // -> x

    // ===== Block 2: knowledge retriever (q/k from x, v from y, mask0 strict, FFN) =====
    run_gemm(gx, Wk + 2 * DD, bk + 2 * PD, gq, PM, PD, PD, false);
    run_gemm(gy, Wv + 2 * DD, bv + 2 * PD, gv, PM, PD, PD, false);
    attn_kernel<<<attnGrid, 256, ATT_SMEM>>>(gq, gv, gam, 2, /*strict=*/1, go);
    run_gemm(go, Wo + 2 * DD, bo + 2 * PD, ga, PM, PD, PD, false);
    add_ln_kernel<<<PM, 128>>>(gx, ga, l1g + 2 * PD, l1b + 2 * PD, gt);
    run_gemm(gt, W1 + 2 * DF, b1 + 2 * PF, gh, PM, PF, PD, true);
    run_gemm(gh, W2 + 2 * DF, b2 + 2 * PD, ga, PM, PD, PF, false);
    add_ln_kernel<<<PM, 128>>>(gt, ga, l2g + 2 * PD, l2b + 2 * PD, out);
}

// round 3
// speedup vs baseline: 1.5926x; 1.5926x over previous
#include <cuda_runtime.h>
#include <cuda_bf16.h>
#include <math.h>
#include <stdint.h>

// ---------------- problem constants ----------------
#define PB   16
#define PS   512
#define PD   512
#define PH   8
#define PDK  64
#define PF   2048
#define PM   (PB*PS)          // 8192 rows
#define LN_EPS 1e-5f

// ---------------- scratch (device globals; no allocation) ----------------
__device__ float g_q[(size_t)PM * PD];
__device__ float g_v[(size_t)PM * PD];
__device__ float g_o[(size_t)PM * PD];
__device__ float g_a[(size_t)PM * PD];
__device__ float g_t[(size_t)PM * PD];
__device__ float g_y[(size_t)PM * PD];
__device__ float g_x[(size_t)PM * PD];
__device__ float g_h[(size_t)PM * PF];

// ---------------- helpers ----------------
__device__ __forceinline__ uint32_t smem_u32(const void* p) {
    uint32_t a;
    asm("{ .reg .u64 t; cvta.to.shared.u64 t, %1; cvt.u32.u64 %0, t; }"
        : "=r"(a) : "l"(p));
    return a;
}
__device__ __forceinline__ float warpMax(float v) {
#pragma unroll
    for (int o = 16; o; o >>= 1) v = fmaxf(v, __shfl_xor_sync(0xffffffffu, v, o));
    return v;
}
__device__ __forceinline__ float warpSum(float v) {
#pragma unroll
    for (int o = 16; o; o >>= 1) v += __shfl_xor_sync(0xffffffffu, v, o);
    return v;
}

// split fp32 (x,y) into packed bf16 hi pair (return) and lo pair (out param)
__device__ __forceinline__ uint32_t split_pack(float x, float y, uint32_t& lo_pack) {
    __nv_bfloat16 hx = __float2bfloat16_rn(x);
    __nv_bfloat16 hy = __float2bfloat16_rn(y);
    float rx = x - __bfloat162float(hx);
    float ry = y - __bfloat162float(hy);
    __nv_bfloat16 lx = __float2bfloat16_rn(rx);
    __nv_bfloat16 ly = __float2bfloat16_rn(ry);
    lo_pack = ((uint32_t)__bfloat16_as_ushort(ly) << 16) | (uint32_t)__bfloat16_as_ushort(lx);
    return ((uint32_t)__bfloat16_as_ushort(hy) << 16) | (uint32_t)__bfloat16_as_ushort(hx);
}

__device__ __forceinline__ void ldsm_x4(uint32_t& r0, uint32_t& r1, uint32_t& r2,
                                        uint32_t& r3, uint32_t addr) {
    asm volatile("ldmatrix.sync.aligned.m8n8.x4.shared.b16 {%0,%1,%2,%3}, [%4];"
                 : "=r"(r0), "=r"(r1), "=r"(r2), "=r"(r3) : "r"(addr));
}
__device__ __forceinline__ void ldsm_x2t(uint32_t& r0, uint32_t& r1, uint32_t addr) {
    asm volatile("ldmatrix.sync.aligned.m8n8.x2.trans.shared.b16 {%0,%1}, [%2];"
                 : "=r"(r0), "=r"(r1) : "r"(addr));
}
__device__ __forceinline__ void mma_bf16(float c[4], uint32_t a0, uint32_t a1,
                                         uint32_t a2, uint32_t a3,
                                         uint32_t b0, uint32_t b1) {
    asm volatile(
        "mma.sync.aligned.m16n8k16.row.col.f32.bf16.bf16.f32 "
        "{%0,%1,%2,%3}, {%4,%5,%6,%7}, {%8,%9}, {%0,%1,%2,%3};"
        : "+f"(c[0]), "+f"(c[1]), "+f"(c[2]), "+f"(c[3])
        : "r"(a0), "r"(a1), "r"(a2), "r"(a3), "r"(b0), "r"(b1));
}

// ======================= bf16x3 tensor-core GEMM =======================
// C[M,N] = A[M,K] @ W[K,N] + bias, optional ReLU.
// CTA tile 128x128, K-chunk 32, 256 threads (8 warps, 2x4 of 64x32 warp tiles).
// SMEM stage layout (bytes):
//   A_hi: 128 rows x 80B (32 bf16 + pad)         [0,     10240)
//   A_lo:                                         [10240, 20480)
//   B_hi: 32 rows (k) x 272B (128 bf16 + pad)     [20480, 29184)
//   B_lo:                                         [29184, 37888)
#define SA_HI 0
#define SA_LO 10240
#define SB_HI 20480
#define SB_LO 29184
#define STAGE 38912
#define GEMM_SMEM (2 * STAGE)

template <int RELU>
__global__ __launch_bounds__(256, 1)
void gemm_mma(const float* __restrict__ A, const float* __restrict__ W,
              const float* __restrict__ bias, float* __restrict__ C,
              int Mv, int Nv, int Kv)
{
    extern __shared__ __align__(1024) char smem_raw[];
    const uint32_t smb = smem_u32(smem_raw);
    const int tid = threadIdx.x;
    const int lane = tid & 31;
    const int wid = tid >> 5;
    const int wm = (wid >> 2) * 64;   // warp m offset in tile
    const int wn = (wid & 3) * 32;    // warp n offset in tile
    const int by = blockIdx.y * 128;
    const int bx = blockIdx.x * 128;
    const int nC = Kv >> 5;

    float c[4][4][4] = {};
    float4 aR[4], bR[4];

    // A ldmatrix per-lane address components (x4: quads over lanes)
    const int aRow = (lane & 7) + ((lane >> 3) & 1) * 8;  // row within 16
    const int aCol = (lane >> 4) * 8;                     // k offset within 16
    // B ldmatrix per-lane address component (x2.trans: lanes 0-15)
    const int bRow = lane & 15;                           // k offset within 16

    // ---- LDG chunk into regs ----
    auto ldg = [&](int ck) {
        const int k0 = ck * 32;
        const float* Ab = A + (size_t)by * Kv + k0;
        const float* Wb = W + (size_t)k0 * Nv + bx;
#pragma unroll
        for (int j = 0; j < 4; j++) {
            int idx = tid + j * 256;
            aR[j] = *(const float4*)(Ab + (size_t)(idx >> 3) * Kv + (idx & 7) * 4);
            bR[j] = *(const float4*)(Wb + (size_t)(idx >> 5) * Nv + (idx & 31) * 4);
        }
    };
    // ---- convert + STS into stage buffer b ----
    auto sts = [&](int b) {
        char* stg = smem_raw + b * STAGE;
#pragma unroll
        for (int j = 0; j < 4; j++) {
            int idx = tid + j * 256;
            {   // A: row m, 4 floats at k = (idx&7)*4
                int m = idx >> 3, kq = idx & 7;
                uint2 hw, lw;
                hw.x = split_pack(aR[j].x, aR[j].y, lw.x);
                hw.y = split_pack(aR[j].z, aR[j].w, lw.y);
                *(uint2*)(stg + SA_HI + m * 80 + kq * 8) = hw;
                *(uint2*)(stg + SA_LO + m * 80 + kq * 8) = lw;
            }
            {   // B: row k, 4 floats at n = (idx&31)*4
                int k = idx >> 5, nq = idx & 31;
                uint2 hw, lw;
                hw.x = split_pack(bR[j].x, bR[j].y, lw.x);
                hw.y = split_pack(bR[j].z, bR[j].w, lw.y);
                *(uint2*)(stg + SB_HI + k * 272 + nq * 8) = hw;
                *(uint2*)(stg + SB_LO + k * 272 + nq * 8) = lw;
            }
        }
    };
    // ---- compute one chunk from stage buffer b ----
    auto compute = [&](int b) {
        const uint32_t sa_hi = smb + b * STAGE + SA_HI;
        const uint32_t sa_lo = smb + b * STAGE + SA_LO;
        const uint32_t sb_hi = smb + b * STAGE + SB_HI;
        const uint32_t sb_lo = smb + b * STAGE + SB_LO;
#pragma unroll
        for (int ks = 0; ks < 32; ks += 16) {
            uint32_t ah[4][4], al[4][4], bh[4][2], bl[4][2];
#pragma unroll
            for (int mt = 0; mt < 4; mt++) {
                uint32_t off = (uint32_t)((wm + mt * 16 + aRow) * 80 + (ks + aCol) * 2);
                ldsm_x4(ah[mt][0], ah[mt][1], ah[mt][2], ah[mt][3], sa_hi + off);
                ldsm_x4(al[mt][0], al[mt][1], al[mt][2], al[mt][3], sa_lo + off);
            }
#pragma unroll
            for (int nt = 0; nt < 4; nt++) {
                uint32_t off = (uint32_t)((ks + bRow) * 272 + (wn + nt * 8) * 2);
                ldsm_x2t(bh[nt][0], bh[nt][1], sb_hi + off);
                ldsm_x2t(bl[nt][0], bl[nt][1], sb_lo + off);
            }
#pragma unroll
            for (int mt = 0; mt < 4; mt++)
#pragma unroll
                for (int nt = 0; nt < 4; nt++) {
                    mma_bf16(c[mt][nt], ah[mt][0], ah[mt][1], ah[mt][2], ah[mt][3],
                             bh[nt][0], bh[nt][1]);
                    mma_bf16(c[mt][nt], ah[mt][0], ah[mt][1], ah[mt][2], ah[mt][3],
                             bl[nt][0], bl[nt][1]);
                    mma_bf16(c[mt][nt], al[mt][0], al[mt][1], al[mt][2], al[mt][3],
                             bh[nt][0], bh[nt][1]);
                }
        }
    };

    // ---- software pipeline ----
    ldg(0);
    sts(0);
    __syncthreads();
    for (int ck = 0; ck < nC; ck++) {
        if (ck + 1 < nC) ldg(ck + 1);
        compute(ck & 1);
        if (ck + 1 < nC) {
            sts((ck + 1) & 1);
            __syncthreads();
        }
    }

    // ---- epilogue ----
    const int g = lane >> 2, t = lane & 3;
#pragma unroll
    for (int mt = 0; mt < 4; mt++) {
#pragma unroll
        for (int nt = 0; nt < 4; nt++) {
            int row = by + wm + mt * 16 + g;
            int col = bx + wn + nt * 8 + 2 * t;
            float2 bv = *(const float2*)(bias + col);
            float2 v0, v1;
            v0.x = c[mt][nt][0] + bv.x; v0.y = c[mt][nt][1] + bv.y;
            v1.x = c[mt][nt][2] + bv.x; v1.y = c[mt][nt][3] + bv.y;
            if (RELU) {
                v0.x = fmaxf(v0.x, 0.f); v0.y = fmaxf(v0.y, 0.f);
                v1.x = fmaxf(v1.x, 0.f); v1.y = fmaxf(v1.y, 0.f);
            }
            *(float2*)(C + (size_t)row * Nv + col) = v0;
            *(float2*)(C + (size_t)(row + 8) * Nv + col) = v1;
        }
    }
}

// ---------------- fused add + LayerNorm ----------------
__global__ __launch_bounds__(128) void add_ln_kernel(
    const float* __restrict__ A, const float* __restrict__ Bv,
    const float* __restrict__ g, const float* __restrict__ be,
    float* __restrict__ out)
{
    __shared__ float red[16];
    const int row = blockIdx.x;
    const int tid = threadIdx.x;
    const int lane = tid & 31, wid = tid >> 5;
    float4 xa = ((const float4*)(A  + (size_t)row * PD))[tid];
    float4 xb = ((const float4*)(Bv + (size_t)row * PD))[tid];
    float x0 = xa.x + xb.x, x1 = xa.y + xb.y, x2 = xa.z + xb.z, x3 = xa.w + xb.w;

    float s = warpSum(x0 + x1 + x2 + x3);
    if (lane == 0) red[wid] = s;
    __syncthreads();
    float mean = (red[0] + red[1] + red[2] + red[3]) * (1.0f / PD);

    float d0 = x0 - mean, d1 = x1 - mean, d2 = x2 - mean, d3 = x3 - mean;
    float vs = warpSum(d0 * d0 + d1 * d1 + d2 * d2 + d3 * d3);
    if (lane == 0) red[8 + wid] = vs;
    __syncthreads();
    float var = (red[8] + red[9] + red[10] + red[11]) * (1.0f / PD);
    float rstd = rsqrtf(var + LN_EPS);

    float4 gg = ((const float4*)g)[tid];
    float4 bb = ((const float4*)be)[tid];
    float4 o;
    o.x = d0 * rstd * gg.x + bb.x;
    o.y = d1 * rstd * gg.y + bb.y;
    o.z = d2 * rstd * gg.z + bb.z;
    o.w = d3 * rstd * gg.w + bb.w;
    ((float4*)(out + (size_t)row * PD))[tid] = o;
}

// ---------------- fused distance-decay attention ----------------
#define ATT_ROWS 32
#define ATT_JT   128
#define SS_LD    516
#define KV_LD    68
#define ATT_SMEM ((ATT_ROWS*64 + ATT_ROWS*SS_LD + ATT_JT*KV_LD) * 4)

__global__ __launch_bounds__(256) void attn_kernel(
    const float* __restrict__ Q, const float* __restrict__ V,
    const float* __restrict__ gammas, int layer, int strict,
    float* __restrict__ O)
{
    extern __shared__ float sm[];
    float* sQ  = sm;
    float* sS  = sQ + ATT_ROWS * 64;
    float* sKV = sS + ATT_ROWS * SS_LD;

    const int bh = blockIdx.x;
    const int b = bh >> 3, h = bh & 7;
    const int i0 = blockIdx.y * ATT_ROWS;
    const int tid = threadIdx.x;
    const int lane = tid & 31, w = tid >> 5;

    float gamma = gammas[layer * PH + h];
    float gneg = (gamma > 20.f) ? -gamma : -log1pf(expf(gamma));

    const float* Qb = Q + (size_t)(b * PS) * PD + h * PDK;
    const float* Vb = V + (size_t)(b * PS) * PD + h * PDK;

    for (int idx = tid; idx < ATT_ROWS * PDK; idx += 256) {
        int r = idx >> 6, d = idx & 63;
        sQ[r * 64 + d] = Qb[(size_t)(i0 + r) * PD + d];
    }
    __syncthreads();

    {
        const int ty = tid >> 5;
        const int tx = tid & 31;
        const int ib = ty * 4, jb = tx * 4;
        for (int j0 = 0; j0 < PS; j0 += ATT_JT) {
            for (int idx = tid; idx < ATT_JT * PDK; idx += 256) {
                int r = idx >> 6, d = idx & 63;
                sKV[r * KV_LD + d] = Qb[(size_t)(j0 + r) * PD + d];
            }
            __syncthreads();
            float acc[4][4] = {};
#pragma unroll 8
            for (int k = 0; k < PDK; k++) {
                float a0 = sQ[(ib + 0) * 64 + k];
                float a1 = sQ[(ib + 1) * 64 + k];
                float a2 = sQ[(ib + 2) * 64 + k];
                float a3 = sQ[(ib + 3) * 64 + k];
                float b0 = sKV[(jb + 0) * KV_LD + k];
                float b1 = sKV[(jb + 1) * KV_LD + k];
                float b2 = sKV[(jb + 2) * KV_LD + k];
                float b3 = sKV[(jb + 3) * KV_LD + k];
                acc[0][0] += a0 * b0; acc[0][1] += a0 * b1; acc[0][2] += a0 * b2; acc[0][3] += a0 * b3;
                acc[1][0] += a1 * b0; acc[1][1] += a1 * b1; acc[1][2] += a1 * b2; acc[1][3] += a1 * b3;
                acc[2][0] += a2 * b0; acc[2][1] += a2 * b1; acc[2][2] += a2 * b2; acc[2][3] += a2 * b3;
                acc[3][0] += a3 * b0; acc[3][1] += a3 * b1; acc[3][2] += a3 * b2; acc[3][3] += a3 * b3;
            }
            const float scale = 0.125f;
#pragma unroll
            for (int ii = 0; ii < 4; ii++)
#pragma unroll
                for (int jj = 0; jj < 4; jj++)
                    sS[(ib + ii) * SS_LD + j0 + jb + jj] = acc[ii][jj] * scale;
            __syncthreads();
        }
    }

    const float NEG = -1e32f;
    for (int rr = 0; rr < 4; rr++) {
        const int il = w + rr * 8;
        const int ig = i0 + il;
        float sraw[16], p[16], cum[16];
        float mx = NEG;
#pragma unroll
        for (int c = 0; c < 16; c++) {
            int j = lane + 32 * c;
            sraw[c] = sS[il * SS_LD + j];
            bool vld = strict ? (j < ig) : (j <= ig);
            float s1 = vld ? sraw[c] : NEG;
            p[c] = s1;
            mx = fmaxf(mx, s1);
        }
        mx = warpMax(mx);
        float sum = 0.f;
#pragma unroll
        for (int c = 0; c < 16; c++) { float e = expf(p[c] - mx); p[c] = e; sum += e; }
        sum = warpSum(sum);
        float inv = 1.0f / sum;
#pragma unroll
        for (int c = 0; c < 16; c++) {
            int j = lane + 32 * c;
            bool vld = strict ? (j < ig) : (j <= ig);
            p[c] = vld ? p[c] * inv : 0.f;
        }
        float run = 0.f;
#pragma unroll
        for (int c = 0; c < 16; c++) {
            float sc = p[c];
#pragma unroll
            for (int o = 1; o < 32; o <<= 1) {
                float t = __shfl_up_sync(0xffffffffu, sc, o);
                if (lane >= o) sc += t;
            }
            cum[c] = run + sc;
            run += __shfl_sync(0xffffffffu, sc, 31);
        }
        const float tot = run;
        float m2 = NEG;
#pragma unroll
        for (int c = 0; c < 16; c++) {
            int j = lane + 32 * c;
            bool vld = strict ? (j < ig) : (j <= ig);
            float pos = fabsf((float)(ig - j));
            float dist = sqrtf(fmaxf((tot - cum[c]) * pos, 0.f));
            float eff = expf(gneg * dist);
            eff = fminf(fmaxf(eff, 1e-5f), 1e5f);
            float v2 = vld ? sraw[c] * eff : NEG;
            p[c] = v2;
            m2 = fmaxf(m2, v2);
        }
        m2 = warpMax(m2);
        float sum2 = 0.f;
#pragma unroll
        for (int c = 0; c < 16; c++) { float e = expf(p[c] - m2); p[c] = e; sum2 += e; }
        sum2 = warpSum(sum2);
        float inv2 = 1.0f / sum2;
#pragma unroll
        for (int c = 0; c < 16; c++)
            sS[il * SS_LD + lane + 32 * c] = p[c] * inv2;
    }
    __syncthreads();

    {
        const int tx = tid & 15;
        const int ty = tid >> 4;
        const int ib = ty * 2, db = tx * 4;
        float acc[2][4] = {};
        for (int j0 = 0; j0 < PS; j0 += ATT_JT) {
            for (int idx = tid; idx < ATT_JT * PDK; idx += 256) {
                int r = idx >> 6, d = idx & 63;
                sKV[r * KV_LD + d] = Vb[(size_t)(j0 + r) * PD + d];
            }
            __syncthreads();
#pragma unroll 4
            for (int jj = 0; jj < ATT_JT; jj++) {
                float a0 = sS[(ib + 0) * SS_LD + j0 + jj];
                float a1 = sS[(ib + 1) * SS_LD + j0 + jj];
                float4 v4 = *(const float4*)&sKV[jj * KV_LD + db];
                acc[0][0] += a0 * v4.x; acc[0][1] += a0 * v4.y;
                acc[0][2] += a0 * v4.z; acc[0][3] += a0 * v4.w;
                acc[1][0] += a1 * v4.x; acc[1][1] += a1 * v4.y;
                acc[1][2] += a1 * v4.z; acc[1][3] += a1 * v4.w;
            }
            __syncthreads();
        }
        float* Ob = O + (size_t)(b * PS + i0) * PD + h * PDK;
#pragma unroll
        for (int ii = 0; ii < 2; ii++)
            *(float4*)&Ob[(size_t)(ib + ii) * PD + db] =
                make_float4(acc[ii][0], acc[ii][1], acc[ii][2], acc[ii][3]);
    }
}

// ---------------- host orchestration ----------------
static void run_gemm(const float* A, const float* W, const float* bias, float* C,
                     int Mv, int Nv, int Kv, bool relu)
{
    dim3 grid(Nv / 128, Mv / 128);
    if (relu) gemm_mma<1><<<grid, 256, GEMM_SMEM>>>(A, W, bias, C, Mv, Nv, Kv);
    else      gemm_mma<0><<<grid, 256, GEMM_SMEM>>>(A, W, bias, C, Mv, Nv, Kv);
}

extern "C" void kernel_launch(void* const* d_in, const int* in_sizes, int n_in,
                              void* d_out, int out_size)
{
    const float* q_embed  = (const float*)d_in[0];
    const float* qa_embed = (const float*)d_in[1];
    const float* Wk  = (const float*)d_in[2];
    const float* bk  = (const float*)d_in[3];
    const float* Wv  = (const float*)d_in[4];
    const float* bv  = (const float*)d_in[5];
    const float* Wo  = (const float*)d_in[6];
    const float* bo  = (const float*)d_in[7];
    const float* gam = (const float*)d_in[8];
    const float* l1g = (const float*)d_in[9];
    const float* l1b = (const float*)d_in[10];
    const float* W1  = (const float*)d_in[11];
    const float* b1  = (const float*)d_in[12];
    const float* W2  = (const float*)d_in[13];
    const float* b2  = (const float*)d_in[14];
    const float* l2g = (const float*)d_in[15];
    const float* l2b = (const float*)d_in[16];
    float* out = (float*)d_out;

    float *gq, *gv, *go, *ga, *gt, *gy, *gx, *gh;
    cudaGetSymbolAddress((void**)&gq, g_q);
    cudaGetSymbolAddress((void**)&gv, g_v);
    cudaGetSymbolAddress((void**)&go, g_o);
    cudaGetSymbolAddress((void**)&ga, g_a);
    cudaGetSymbolAddress((void**)&gt, g_t);
    cudaGetSymbolAddress((void**)&gy, g_y);
    cudaGetSymbolAddress((void**)&gx, g_x);
    cudaGetSymbolAddress((void**)&gh, g_h);

    cudaFuncSetAttribute(attn_kernel, cudaFuncAttributeMaxDynamicSharedMemorySize, ATT_SMEM);
    cudaFuncSetAttribute(gemm_mma<0>, cudaFuncAttributeMaxDynamicSharedMemorySize, GEMM_SMEM);
    cudaFuncSetAttribute(gemm_mma<1>, cudaFuncAttributeMaxDynamicSharedMemorySize, GEMM_SMEM);

    const size_t DD = (size_t)PD * PD, DF = (size_t)PD * PF;
    dim3 attnGrid(PB * PH, PS / ATT_ROWS);

    // ===== Block 0: knowledge encoder (qa_embed, mask1, FFN) =====
    run_gemm(qa_embed, Wk + 0 * DD, bk + 0 * PD, gq, PM, PD, PD, false);
    run_gemm(qa_embed, Wv + 0 * DD, bv + 0 * PD, gv, PM, PD, PD, false);
    attn_kernel<<<attnGrid, 256, ATT_SMEM>>>(gq, gv, gam, 0, 0, go);
    run_gemm(go, Wo + 0 * DD, bo + 0 * PD, ga, PM, PD, PD, false);
    add_ln_kernel<<<PM, 128>>>(qa_embed, ga, l1g + 0 * PD, l1b + 0 * PD, gt);
    run_gemm(gt, W1 + 0 * DF, b1 + 0 * PF, gh, PM, PF, PD, true);
    run_gemm(gh, W2 + 0 * DF, b2 + 0 * PD, ga, PM, PD, PF, false);
    add_ln_kernel<<<PM, 128>>>(gt, ga, l2g + 0 * PD, l2b + 0 * PD, gy);

    // ===== Block 1: question encoder (q_embed, mask1, no FFN) =====
    run_gemm(q_embed, Wk + 1 * DD, bk + 1 * PD, gq, PM, PD, PD, false);
    run_gemm(q_embed, Wv + 1 * DD, bv + 1 * PD, gv, PM, PD, PD, false);
    attn_kernel<<<attnGrid, 256, ATT_SMEM>>>(gq, gv, gam, 1, 0, go);
    run_gemm(go, Wo + 1 * DD, bo + 1 * PD, ga, PM, PD, PD, false);
    add_ln_kernel<<<PM, 128>>>(q_embed, ga, l1g + 1 * PD, l1b + 1 * PD, gx);

    // ===== Block 2: knowledge retriever (q/k from x, v from y, strict mask, FFN) =====
    run_gemm(gx, Wk + 2 * DD, bk + 2 * PD, gq, PM, PD, PD, false);
    run_gemm(gy, Wv + 2 * DD, bv + 2 * PD, gv, PM, PD, PD, false);
    attn_kernel<<<attnGrid, 256, ATT_SMEM>>>(gq, gv, gam, 2, 1, go);
    run_gemm(go, Wo + 2 * DD, bo + 2 * PD, ga, PM, PD, PD, false);
    add_ln_kernel<<<PM, 128>>>(gx, ga, l1g + 2 * PD, l1b + 2 * PD, gt);
    run_gemm(gt, W1 + 2 * DF, b1 + 2 * PF, gh, PM, PF, PD, true);
    run_gemm(gh, W2 + 2 * DF, b2 + 2 * PD, ga, PM, PD, PF, false);
    add_ln_kernel<<<PM, 128>>>(gt, ga, l2g + 2 * PD, l2b + 2 * PD, out);
}

// round 4
// speedup vs baseline: 2.2834x; 1.4337x over previous
#include <cuda_runtime.h>
#include <cuda_bf16.h>
#include <math.h>
#include <stdint.h>

// ---------------- problem constants ----------------
#define PB   16
#define PS   512
#define PD   512
#define PH   8
#define PDK  64
#define PF   2048
#define PM   (PB*PS)          // 8192 rows
#define LN_EPS 1e-5f
typedef __nv_bfloat16 bf16;

// ---------------- scratch (device globals; no allocation) ----------------
__device__ float g_a[(size_t)PM * PD];
__device__ float g_t[(size_t)PM * PD];
__device__ float g_x[(size_t)PM * PD];

// bf16 hi/lo pair planes
__device__ bf16 p_e1h[(size_t)PM*PD], p_e1l[(size_t)PM*PD];
__device__ bf16 p_e2h[(size_t)PM*PD], p_e2l[(size_t)PM*PD];
__device__ bf16 p_qh[(size_t)PM*PD],  p_ql[(size_t)PM*PD];
__device__ bf16 p_vh[(size_t)PM*PD],  p_vl[(size_t)PM*PD];
__device__ bf16 p_oh[(size_t)PM*PD],  p_ol[(size_t)PM*PD];
__device__ bf16 p_th[(size_t)PM*PD],  p_tl[(size_t)PM*PD];
__device__ bf16 p_yh[(size_t)PM*PD],  p_yl[(size_t)PM*PD];
__device__ bf16 p_xh[(size_t)PM*PD],  p_xl[(size_t)PM*PD];
__device__ bf16 p_hh[(size_t)PM*PF],  p_hl[(size_t)PM*PF];
__device__ bf16 p_wkh[(size_t)3*PD*PD], p_wkl[(size_t)3*PD*PD];
__device__ bf16 p_wvh[(size_t)3*PD*PD], p_wvl[(size_t)3*PD*PD];
__device__ bf16 p_woh[(size_t)3*PD*PD], p_wol[(size_t)3*PD*PD];
__device__ bf16 p_w1h[(size_t)3*PD*PF], p_w1l[(size_t)3*PD*PF];
__device__ bf16 p_w2h[(size_t)3*PF*PD], p_w2l[(size_t)3*PF*PD];

// ---------------- helpers ----------------
__device__ __forceinline__ uint32_t smem_u32(const void* p) {
    uint32_t a;
    asm("{ .reg .u64 t; cvta.to.shared.u64 t, %1; cvt.u32.u64 %0, t; }"
        : "=r"(a) : "l"(p));
    return a;
}
__device__ __forceinline__ float warpMax(float v) {
#pragma unroll
    for (int o = 16; o; o >>= 1) v = fmaxf(v, __shfl_xor_sync(0xffffffffu, v, o));
    return v;
}
__device__ __forceinline__ float warpSum(float v) {
#pragma unroll
    for (int o = 16; o; o >>= 1) v += __shfl_xor_sync(0xffffffffu, v, o);
    return v;
}
__device__ __forceinline__ uint32_t split_pack(float x, float y, uint32_t& lo_pack) {
    bf16 hx = __float2bfloat16_rn(x);
    bf16 hy = __float2bfloat16_rn(y);
    bf16 lx = __float2bfloat16_rn(x - __bfloat162float(hx));
    bf16 ly = __float2bfloat16_rn(y - __bfloat162float(hy));
    lo_pack = ((uint32_t)__bfloat16_as_ushort(ly) << 16) | (uint32_t)__bfloat16_as_ushort(lx);
    return ((uint32_t)__bfloat16_as_ushort(hy) << 16) | (uint32_t)__bfloat16_as_ushort(hx);
}
__device__ __forceinline__ void ldsm_x4(uint32_t* r, uint32_t addr) {
    asm volatile("ldmatrix.sync.aligned.m8n8.x4.shared.b16 {%0,%1,%2,%3}, [%4];"
                 : "=r"(r[0]), "=r"(r[1]), "=r"(r[2]), "=r"(r[3]) : "r"(addr));
}
__device__ __forceinline__ void ldsm_x2(uint32_t* r, uint32_t addr) {
    asm volatile("ldmatrix.sync.aligned.m8n8.x2.shared.b16 {%0,%1}, [%2];"
                 : "=r"(r[0]), "=r"(r[1]) : "r"(addr));
}
__device__ __forceinline__ void ldsm_x2t(uint32_t* r, uint32_t addr) {
    asm volatile("ldmatrix.sync.aligned.m8n8.x2.trans.shared.b16 {%0,%1}, [%2];"
                 : "=r"(r[0]), "=r"(r[1]) : "r"(addr));
}
__device__ __forceinline__ void mma_bf16(float c[4], const uint32_t a[4], const uint32_t b[2]) {
    asm volatile(
        "mma.sync.aligned.m16n8k16.row.col.f32.bf16.bf16.f32 "
        "{%0,%1,%2,%3}, {%4,%5,%6,%7}, {%8,%9}, {%0,%1,%2,%3};"
        : "+f"(c[0]), "+f"(c[1]), "+f"(c[2]), "+f"(c[3])
        : "r"(a[0]), "r"(a[1]), "r"(a[2]), "r"(a[3]), "r"(b[0]), "r"(b[1]));
}
__device__ __forceinline__ void cp16(uint32_t dst, const void* src) {
    asm volatile("cp.async.cg.shared.global [%0], [%1], 16;"
                 :: "r"(dst), "l"(src) : "memory");
}
#define CP_COMMIT() asm volatile("cp.async.commit_group;" ::: "memory")
#define CP_WAIT1()  asm volatile("cp.async.wait_group 1;" ::: "memory")

// ---------------- fp32 -> bf16 hi/lo conversion ----------------
__global__ __launch_bounds__(256) void conv_pair(
    const float* __restrict__ src, bf16* __restrict__ h, bf16* __restrict__ l, int n4)
{
    int i = blockIdx.x * 256 + threadIdx.x;
    if (i < n4) {
        float4 v = ((const float4*)src)[i];
        uint32_t lo0, lo1;
        uint32_t h0 = split_pack(v.x, v.y, lo0);
        uint32_t h1 = split_pack(v.z, v.w, lo1);
        ((uint2*)h)[i] = make_uint2(h0, h1);
        ((uint2*)l)[i] = make_uint2(lo0, lo1);
    }
}

// ======================= bf16x3 tensor-core GEMM (cp.async) =======================
// C[M,N] = A[M,K] @ W[K,N] + bias. A,W preconverted bf16 hi/lo planes.
// OUTMODE: 0 = fp32, 1 = bf16 pair, 2 = bf16 pair + ReLU.
// Tile 128x128, K-chunk 32, 3-stage cp.async, 256 threads (8 warps 2x4 of 64x32).
#define SA_HI 0
#define SA_LO 10240
#define SB_HI 20480
#define SB_LO 29184
#define STAGE 37888
#define GEMM_SMEM (3 * STAGE)

template <int OUTMODE>
__global__ __launch_bounds__(256, 1)
void gemm_mma(const bf16* __restrict__ Ah, const bf16* __restrict__ Al,
              const bf16* __restrict__ Wh, const bf16* __restrict__ Wl,
              const float* __restrict__ bias,
              float* __restrict__ C, bf16* __restrict__ Ch, bf16* __restrict__ Cl,
              int Mv, int Nv, int Kv)
{
    extern __shared__ __align__(128) char smem_raw[];
    const uint32_t smb = smem_u32(smem_raw);
    const int tid = threadIdx.x;
    const int lane = tid & 31;
    const int wid = tid >> 5;
    const int wm = (wid >> 2) * 64;
    const int wn = (wid & 3) * 32;
    const int by = blockIdx.y * 128;
    const int bx = blockIdx.x * 128;
    const int nC = Kv >> 5;

    float c[4][4][4] = {};
    const int aRow = (lane & 7) + ((lane >> 3) & 1) * 8;
    const int aCol = (lane >> 4) * 8;
    const int bRow = lane & 15;

    auto issue = [&](int ck) {
        const uint32_t sb = smb + (ck % 3) * STAGE;
        const int k0 = ck * 32;
#pragma unroll
        for (int i = 0; i < 2; i++) {
            int idx = tid + i * 256;
            int r = idx >> 2, s = idx & 3;
            size_t go = (size_t)(by + r) * Kv + k0 + s * 8;
            cp16(sb + SA_HI + r * 80 + s * 16, Ah + go);
            cp16(sb + SA_LO + r * 80 + s * 16, Al + go);
        }
#pragma unroll
        for (int i = 0; i < 2; i++) {
            int idx = tid + i * 256;
            int r = idx >> 4, s = idx & 15;
            size_t go = (size_t)(k0 + r) * Nv + bx + s * 8;
            cp16(sb + SB_HI + r * 272 + s * 16, Wh + go);
            cp16(sb + SB_LO + r * 272 + s * 16, Wl + go);
        }
        CP_COMMIT();
    };

    issue(0);
    issue(1);

    for (int ck = 0; ck < nC; ck++) {
        CP_WAIT1();
        __syncthreads();
        if (ck + 2 < nC) issue(ck + 2);

        const uint32_t sb = smb + (ck % 3) * STAGE;
#pragma unroll
        for (int ks = 0; ks < 32; ks += 16) {
            uint32_t ah[4][4], al[4][4], bh[4][2], bl[4][2];
#pragma unroll
            for (int mt = 0; mt < 4; mt++) {
                uint32_t off = (uint32_t)((wm + mt * 16 + aRow) * 80 + (ks + aCol) * 2);
                ldsm_x4(ah[mt], sb + SA_HI + off);
                ldsm_x4(al[mt], sb + SA_LO + off);
            }
#pragma unroll
            for (int nt = 0; nt < 4; nt++) {
                uint32_t off = (uint32_t)((ks + bRow) * 272 + (wn + nt * 8) * 2);
                ldsm_x2t(bh[nt], sb + SB_HI + off);
                ldsm_x2t(bl[nt], sb + SB_LO + off);
            }
#pragma unroll
            for (int mt = 0; mt < 4; mt++)
#pragma unroll
                for (int nt = 0; nt < 4; nt++) {
                    mma_bf16(c[mt][nt], ah[mt], bh[nt]);
                    mma_bf16(c[mt][nt], ah[mt], bl[nt]);
                    mma_bf16(c[mt][nt], al[mt], bh[nt]);
                }
        }
    }

    // ---- epilogue ----
    const int g = lane >> 2, t = lane & 3;
#pragma unroll
    for (int mt = 0; mt < 4; mt++) {
#pragma unroll
        for (int nt = 0; nt < 4; nt++) {
            int row = by + wm + mt * 16 + g;
            int col = bx + wn + nt * 8 + 2 * t;
            float2 bv = *(const float2*)(bias + col);
            float v00 = c[mt][nt][0] + bv.x, v01 = c[mt][nt][1] + bv.y;
            float v10 = c[mt][nt][2] + bv.x, v11 = c[mt][nt][3] + bv.y;
            if (OUTMODE == 2) {
                v00 = fmaxf(v00, 0.f); v01 = fmaxf(v01, 0.f);
                v10 = fmaxf(v10, 0.f); v11 = fmaxf(v11, 0.f);
            }
            if (OUTMODE == 0) {
                *(float2*)(C + (size_t)row * Nv + col) = make_float2(v00, v01);
                *(float2*)(C + (size_t)(row + 8) * Nv + col) = make_float2(v10, v11);
            } else {
                uint32_t lo0, lo1;
                uint32_t h0 = split_pack(v00, v01, lo0);
                uint32_t h1 = split_pack(v10, v11, lo1);
                *(uint32_t*)(Ch + (size_t)row * Nv + col) = h0;
                *(uint32_t*)(Cl + (size_t)row * Nv + col) = lo0;
                *(uint32_t*)(Ch + (size_t)(row + 8) * Nv + col) = h1;
                *(uint32_t*)(Cl + (size_t)(row + 8) * Nv + col) = lo1;
            }
        }
    }
}

// ---------------- fused add + LayerNorm ----------------
// MODE: 0 = fp32 only, 1 = pair only, 2 = both
template <int MODE>
__global__ __launch_bounds__(128) void add_ln_kernel(
    const float* __restrict__ A, const float* __restrict__ Bv,
    const float* __restrict__ g, const float* __restrict__ be,
    float* __restrict__ outF, bf16* __restrict__ outH, bf16* __restrict__ outL)
{
    __shared__ float red[16];
    const int row = blockIdx.x;
    const int tid = threadIdx.x;
    const int lane = tid & 31, wid = tid >> 5;
    float4 xa = ((const float4*)(A  + (size_t)row * PD))[tid];
    float4 xb = ((const float4*)(Bv + (size_t)row * PD))[tid];
    float x0 = xa.x + xb.x, x1 = xa.y + xb.y, x2 = xa.z + xb.z, x3 = xa.w + xb.w;

    float s = warpSum(x0 + x1 + x2 + x3);
    if (lane == 0) red[wid] = s;
    __syncthreads();
    float mean = (red[0] + red[1] + red[2] + red[3]) * (1.0f / PD);

    float d0 = x0 - mean, d1 = x1 - mean, d2 = x2 - mean, d3 = x3 - mean;
    float vs = warpSum(d0 * d0 + d1 * d1 + d2 * d2 + d3 * d3);
    if (lane == 0) red[8 + wid] = vs;
    __syncthreads();
    float var = (red[8] + red[9] + red[10] + red[11]) * (1.0f / PD);
    float rstd = rsqrtf(var + LN_EPS);

    float4 gg = ((const float4*)g)[tid];
    float4 bb = ((const float4*)be)[tid];
    float o0 = d0 * rstd * gg.x + bb.x;
    float o1 = d1 * rstd * gg.y + bb.y;
    float o2 = d2 * rstd * gg.z + bb.z;
    float o3 = d3 * rstd * gg.w + bb.w;
    if (MODE != 1)
        ((float4*)(outF + (size_t)row * PD))[tid] = make_float4(o0, o1, o2, o3);
    if (MODE != 0) {
        uint32_t lo0, lo1;
        uint32_t h0 = split_pack(o0, o1, lo0);
        uint32_t h1 = split_pack(o2, o3, lo1);
        ((uint2*)(outH + (size_t)row * PD))[tid] = make_uint2(h0, h1);
        ((uint2*)(outL + (size_t)row * PD))[tid] = make_uint2(lo0, lo1);
    }
}

// ---------------- fused distance-decay attention (tensor-core) ----------------
// CTA: one (b,h) x 32 query rows, 256 threads (8 warps).
// SMEM byte layout:
#define AQ_H 0                       // 32 x 144B
#define AQ_L 4608
#define AK_H 9216                    // 128 x 144B  (K then V chunks)
#define AK_L 27648
#define A_SS 46080                   // 32 x 520 fp32
#define AP_H 112640                  // 32 x 520 bf16
#define AP_L 145920
#define ATT_SMEM 179200

__global__ __launch_bounds__(256, 1) void attn_mma(
    const bf16* __restrict__ Qh, const bf16* __restrict__ Ql,
    const bf16* __restrict__ Vh, const bf16* __restrict__ Vl,
    const float* __restrict__ gammas, int layer, int strict,
    bf16* __restrict__ Oh, bf16* __restrict__ Ol)
{
    extern __shared__ __align__(128) char sm_raw[];
    const uint32_t smb = smem_u32(sm_raw);
    float* sS = (float*)(sm_raw + A_SS);

    const int bh = blockIdx.x;
    const int b = bh >> 3, h = bh & 7;
    const int i0 = blockIdx.y * 32;
    const int tid = threadIdx.x;
    const int lane = tid & 31, w = tid >> 5;

    float gamma = gammas[layer * PH + h];
    float gneg = (gamma > 20.f) ? -gamma : -log1pf(expf(gamma));

    const size_t headOff = (size_t)(b * PS) * PD + h * PDK;
    const bf16* Qbh = Qh + headOff;
    const bf16* Qbl = Ql + headOff;
    const bf16* Vbh = Vh + headOff;
    const bf16* Vbl = Vl + headOff;

    const int aRow = (lane & 7) + ((lane >> 3) & 1) * 8;
    const int aCol = (lane >> 4) * 8;
    const int g = lane >> 2, t = lane & 3;

    // load Q tile (32 x 64 bf16, both planes)
    {
        int r = tid >> 3, s = tid & 7;
        *(uint4*)(sm_raw + AQ_H + r * 144 + s * 16) =
            *(const uint4*)(Qbh + (size_t)(i0 + r) * PD + s * 8);
        *(uint4*)(sm_raw + AQ_L + r * 144 + s * 16) =
            *(const uint4*)(Qbl + (size_t)(i0 + r) * PD + s * 8);
    }

    // ---- QK^T pass: warp w covers j-cols [w*16, w*16+16) of each 128-chunk ----
    for (int j0 = 0; j0 < PS; j0 += 128) {
#pragma unroll
        for (int i = 0; i < 4; i++) {
            int idx = tid + i * 256;
            int r = idx >> 3, s = idx & 7;
            *(uint4*)(sm_raw + AK_H + r * 144 + s * 16) =
                *(const uint4*)(Qbh + (size_t)(j0 + r) * PD + s * 8);
            *(uint4*)(sm_raw + AK_L + r * 144 + s * 16) =
                *(const uint4*)(Qbl + (size_t)(j0 + r) * PD + s * 8);
        }
        __syncthreads();

        float acc[2][2][4] = {};
#pragma unroll
        for (int ks = 0; ks < 64; ks += 16) {
            uint32_t ah[2][4], al[2][4], kh[2][2], kl[2][2];
#pragma unroll
            for (int mt = 0; mt < 2; mt++) {
                uint32_t off = (uint32_t)((mt * 16 + aRow) * 144 + (ks + aCol) * 2);
                ldsm_x4(ah[mt], smb + AQ_H + off);
                ldsm_x4(al[mt], smb + AQ_L + off);
            }
#pragma unroll
            for (int nf = 0; nf < 2; nf++) {
                uint32_t off = (uint32_t)((w * 16 + nf * 8 + (lane & 7)) * 144 +
                                          (ks + ((lane >> 3) & 1) * 8) * 2);
                ldsm_x2(kh[nf], smb + AK_H + off);
                ldsm_x2(kl[nf], smb + AK_L + off);
            }
#pragma unroll
            for (int mt = 0; mt < 2; mt++)
#pragma unroll
                for (int nf = 0; nf < 2; nf++) {
                    mma_bf16(acc[mt][nf], ah[mt], kh[nf]);
                    mma_bf16(acc[mt][nf], ah[mt], kl[nf]);
                    mma_bf16(acc[mt][nf], al[mt], kh[nf]);
                }
        }
        const float scale = 0.125f;
#pragma unroll
        for (int mt = 0; mt < 2; mt++)
#pragma unroll
            for (int nf = 0; nf < 2; nf++) {
                int r0 = mt * 16 + g;
                int col = j0 + w * 16 + nf * 8 + 2 * t;
                *(float2*)&sS[r0 * 520 + col] =
                    make_float2(acc[mt][nf][0] * scale, acc[mt][nf][1] * scale);
                *(float2*)&sS[(r0 + 8) * 520 + col] =
                    make_float2(acc[mt][nf][2] * scale, acc[mt][nf][3] * scale);
            }
        __syncthreads();
    }

    // ---- softmax1 -> cumsum -> decay -> softmax2 (warp per row) -> P bf16 pair ----
    const float NEG = -1e32f;
    for (int rr = 0; rr < 4; rr++) {
        const int il = w + rr * 8;
        const int ig = i0 + il;
        float sraw[16], p[16], cum[16];
        float mx = NEG;
#pragma unroll
        for (int c = 0; c < 16; c++) {
            int j = lane + 32 * c;
            sraw[c] = sS[il * 520 + j];
            bool vld = strict ? (j < ig) : (j <= ig);
            float s1 = vld ? sraw[c] : NEG;
            p[c] = s1;
            mx = fmaxf(mx, s1);
        }
        mx = warpMax(mx);
        float sum = 0.f;
#pragma unroll
        for (int c = 0; c < 16; c++) { float e = __expf(p[c] - mx); p[c] = e; sum += e; }
        sum = warpSum(sum);
        float inv = 1.0f / sum;
#pragma unroll
        for (int c = 0; c < 16; c++) {
            int j = lane + 32 * c;
            bool vld = strict ? (j < ig) : (j <= ig);
            p[c] = vld ? p[c] * inv : 0.f;
        }
        float run = 0.f;
#pragma unroll
        for (int c = 0; c < 16; c++) {
            float sc = p[c];
#pragma unroll
            for (int o = 1; o < 32; o <<= 1) {
                float tt = __shfl_up_sync(0xffffffffu, sc, o);
                if (lane >= o) sc += tt;
            }
            cum[c] = run + sc;
            run += __shfl_sync(0xffffffffu, sc, 31);
        }
        const float tot = run;
        float m2 = NEG;
#pragma unroll
        for (int c = 0; c < 16; c++) {
            int j = lane + 32 * c;
            bool vld = strict ? (j < ig) : (j <= ig);
            float pos = fabsf((float)(ig - j));
            float dist = sqrtf(fmaxf((tot - cum[c]) * pos, 0.f));
            float eff = __expf(gneg * dist);
            eff = fminf(fmaxf(eff, 1e-5f), 1e5f);
            float v2 = vld ? sraw[c] * eff : NEG;
            p[c] = v2;
            m2 = fmaxf(m2, v2);
        }
        m2 = warpMax(m2);
        float sum2 = 0.f;
#pragma unroll
        for (int c = 0; c < 16; c++) { float e = __expf(p[c] - m2); p[c] = e; sum2 += e; }
        sum2 = warpSum(sum2);
        float inv2 = 1.0f / sum2;
#pragma unroll
        for (int c = 0; c < 16; c++) {
            int j = lane + 32 * c;
            float val = p[c] * inv2;
            bf16 hi = __float2bfloat16_rn(val);
            bf16 lo = __float2bfloat16_rn(val - __bfloat162float(hi));
            ((unsigned short*)(sm_raw + AP_H))[il * 520 + j] = __bfloat16_as_ushort(hi);
            ((unsigned short*)(sm_raw + AP_L))[il * 520 + j] = __bfloat16_as_ushort(lo);
        }
    }
    __syncthreads();

    // ---- AV pass: warp w -> output d-cols [w*8, w*8+8) ----
    float acco[2][4] = {};
    for (int j0 = 0; j0 < PS; j0 += 128) {
#pragma unroll
        for (int i = 0; i < 4; i++) {
            int idx = tid + i * 256;
            int r = idx >> 3, s = idx & 7;
            *(uint4*)(sm_raw + AK_H + r * 144 + s * 16) =
                *(const uint4*)(Vbh + (size_t)(j0 + r) * PD + s * 8);
            *(uint4*)(sm_raw + AK_L + r * 144 + s * 16) =
                *(const uint4*)(Vbl + (size_t)(j0 + r) * PD + s * 8);
        }
        __syncthreads();
#pragma unroll
        for (int ks = 0; ks < 8; ks++) {
            uint32_t ph[2][4], pl[2][4], vh[2], vl[2];
#pragma unroll
            for (int mt = 0; mt < 2; mt++) {
                uint32_t off = (uint32_t)((mt * 16 + aRow) * 1040 + (j0 + ks * 16 + aCol) * 2);
                ldsm_x4(ph[mt], smb + AP_H + off);
                ldsm_x4(pl[mt], smb + AP_L + off);
            }
            {
                uint32_t off = (uint32_t)((ks * 16 + (lane & 15)) * 144 + (w * 8) * 2);
                ldsm_x2t(vh, smb + AK_H + off);
                ldsm_x2t(vl, smb + AK_L + off);
            }
#pragma unroll
            for (int mt = 0; mt < 2; mt++) {
                mma_bf16(acco[mt], ph[mt], vh);
                mma_bf16(acco[mt], ph[mt], vl);
                mma_bf16(acco[mt], pl[mt], vh);
            }
        }
        __syncthreads();
    }

    // ---- write O as bf16 pair ----
#pragma unroll
    for (int mt = 0; mt < 2; mt++) {
        int r0 = b * PS + i0 + mt * 16 + g;
        int col = h * PDK + w * 8 + 2 * t;
        uint32_t lo0, lo1;
        uint32_t h0 = split_pack(acco[mt][0], acco[mt][1], lo0);
        uint32_t h1 = split_pack(acco[mt][2], acco[mt][3], lo1);
        *(uint32_t*)(Oh + (size_t)r0 * PD + col) = h0;
        *(uint32_t*)(Ol + (size_t)r0 * PD + col) = lo0;
        *(uint32_t*)(Oh + (size_t)(r0 + 8) * PD + col) = h1;
        *(uint32_t*)(Ol + (size_t)(r0 + 8) * PD + col) = lo1;
    }
}

// ---------------- host orchestration ----------------
static void run_gemm(int mode, const bf16* Ah, const bf16* Al,
                     const bf16* Wh, const bf16* Wl, const float* bias,
                     float* C, bf16* Ch, bf16* Cl, int Mv, int Nv, int Kv)
{
    dim3 grid(Nv / 128, Mv / 128);
    if (mode == 0)      gemm_mma<0><<<grid, 256, GEMM_SMEM>>>(Ah, Al, Wh, Wl, bias, C, Ch, Cl, Mv, Nv, Kv);
    else if (mode == 1) gemm_mma<1><<<grid, 256, GEMM_SMEM>>>(Ah, Al, Wh, Wl, bias, C, Ch, Cl, Mv, Nv, Kv);
    else                gemm_mma<2><<<grid, 256, GEMM_SMEM>>>(Ah, Al, Wh, Wl, bias, C, Ch, Cl, Mv, Nv, Kv);
}
static void run_conv(const float* src, bf16* h, bf16* l, size_t n)
{
    int n4 = (int)(n / 4);
    conv_pair<<<(n4 + 255) / 256, 256>>>(src, h, l, n4);
}

extern "C" void kernel_launch(void* const* d_in, const int* in_sizes, int n_in,
                              void* d_out, int out_size)
{
    const float* q_embed  = (const float*)d_in[0];
    const float* qa_embed = (const float*)d_in[1];
    const float* Wk  = (const float*)d_in[2];
    const float* bk  = (const float*)d_in[3];
    const float* Wv  = (const float*)d_in[4];
    const float* bv  = (const float*)d_in[5];
    const float* Wo  = (const float*)d_in[6];
    const float* bo  = (const float*)d_in[7];
    const float* gam = (const float*)d_in[8];
    const float* l1g = (const float*)d_in[9];
    const float* l1b = (const float*)d_in[10];
    const float* W1  = (const float*)d_in[11];
    const float* b1  = (const float*)d_in[12];
    const float* W2  = (const float*)d_in[13];
    const float* b2  = (const float*)d_in[14];
    const float* l2g = (const float*)d_in[15];
    const float* l2b = (const float*)d_in[16];
    float* out = (float*)d_out;

    float *ga, *gt, *gx;
    cudaGetSymbolAddress((void**)&ga, g_a);
    cudaGetSymbolAddress((void**)&gt, g_t);
    cudaGetSymbolAddress((void**)&gx, g_x);
#define SYM(p, s) bf16* p; cudaGetSymbolAddress((void**)&p, s)
    SYM(e1h, p_e1h); SYM(e1l, p_e1l); SYM(e2h, p_e2h); SYM(e2l, p_e2l);
    SYM(qh, p_qh);   SYM(ql, p_ql);   SYM(vh, p_vh);   SYM(vl, p_vl);
    SYM(oh, p_oh);   SYM(ol, p_ol);   SYM(th, p_th);   SYM(tl, p_tl);
    SYM(yh, p_yh);   SYM(yl, p_yl);   SYM(xh, p_xh);   SYM(xl, p_xl);
    SYM(hh, p_hh);   SYM(hl, p_hl);
    SYM(wkh, p_wkh); SYM(wkl, p_wkl); SYM(wvh, p_wvh); SYM(wvl, p_wvl);
    SYM(woh, p_woh); SYM(wol, p_wol); SYM(w1h, p_w1h); SYM(w1l, p_w1l);
    SYM(w2h, p_w2h); SYM(w2l, p_w2l);
#undef SYM

    cudaFuncSetAttribute(attn_mma, cudaFuncAttributeMaxDynamicSharedMemorySize, ATT_SMEM);
    cudaFuncSetAttribute(gemm_mma<0>, cudaFuncAttributeMaxDynamicSharedMemorySize, GEMM_SMEM);
    cudaFuncSetAttribute(gemm_mma<1>, cudaFuncAttributeMaxDynamicSharedMemorySize, GEMM_SMEM);
    cudaFuncSetAttribute(gemm_mma<2>, cudaFuncAttributeMaxDynamicSharedMemorySize, GEMM_SMEM);

    const size_t DD = (size_t)PD * PD, DF = (size_t)PD * PF;
    dim3 attnGrid(PB * PH, PS / 32);

    // ---- preconvert embeds + weights to bf16 hi/lo planes ----
    run_conv(q_embed,  e1h, e1l, (size_t)PM * PD);
    run_conv(qa_embed, e2h, e2l, (size_t)PM * PD);
    run_conv(Wk, wkh, wkl, 3 * DD);
    run_conv(Wv, wvh, wvl, 3 * DD);
    run_conv(Wo, woh, wol, 3 * DD);
    run_conv(W1, w1h, w1l, 3 * DF);
    run_conv(W2, w2h, w2l, 3 * DF);

    // ===== Block 0: knowledge encoder (qa_embed, mask1, FFN) =====
    run_gemm(1, e2h, e2l, wkh + 0 * DD, wkl + 0 * DD, bk + 0 * PD, nullptr, qh, ql, PM, PD, PD);
    run_gemm(1, e2h, e2l, wvh + 0 * DD, wvl + 0 * DD, bv + 0 * PD, nullptr, vh, vl, PM, PD, PD);
    attn_mma<<<attnGrid, 256, ATT_SMEM>>>(qh, ql, vh, vl, gam, 0, 0, oh, ol);
    run_gemm(0, oh, ol, woh + 0 * DD, wol + 0 * DD, bo + 0 * PD, ga, nullptr, nullptr, PM, PD, PD);
    add_ln_kernel<2><<<PM, 128>>>(qa_embed, ga, l1g + 0 * PD, l1b + 0 * PD, gt, th, tl);
    run_gemm(2, th, tl, w1h + 0 * DF, w1l + 0 * DF, b1 + 0 * PF, nullptr, hh, hl, PM, PF, PD);
    run_gemm(0, hh, hl, w2h + 0 * DF, w2l + 0 * DF, b2 + 0 * PD, ga, nullptr, nullptr, PM, PD, PF);
    add_ln_kernel<1><<<PM, 128>>>(gt, ga, l2g + 0 * PD, l2b + 0 * PD, nullptr, yh, yl);

    // ===== Block 1: question encoder (q_embed, mask1, no FFN) =====
    run_gemm(1, e1h, e1l, wkh + 1 * DD, wkl + 1 * DD, bk + 1 * PD, nullptr, qh, ql, PM, PD, PD);
    run_gemm(1, e1h, e1l, wvh + 1 * DD, wvl + 1 * DD, bv + 1 * PD, nullptr, vh, vl, PM, PD, PD);
    attn_mma<<<attnGrid, 256, ATT_SMEM>>>(qh, ql, vh, vl, gam, 1, 0, oh, ol);
    run_gemm(0, oh, ol, woh + 1 * DD, wol + 1 * DD, bo + 1 * PD, ga, nullptr, nullptr, PM, PD, PD);
    add_ln_kernel<2><<<PM, 128>>>(q_embed, ga, l1g + 1 * PD, l1b + 1 * PD, gx, xh, xl);

    // ===== Block 2: knowledge retriever (q/k from x, v from y, strict mask, FFN) =====
    run_gemm(1, xh, xl, wkh + 2 * DD, wkl + 2 * DD, bk + 2 * PD, nullptr, qh, ql, PM, PD, PD);
    run_gemm(1, yh, yl, wvh + 2 * DD, wvl + 2 * DD, bv + 2 * PD, nullptr, vh, vl, PM, PD, PD);
    attn_mma<<<attnGrid, 256, ATT_SMEM>>>(qh, ql, vh, vl, gam, 2, 1, oh, ol);
    run_gemm(0, oh, ol, woh + 2 * DD, wol + 2 * DD, bo + 2 * PD, ga, nullptr, nullptr, PM, PD, PD);
    add_ln_kernel<2><<<PM, 128>>>(gx, ga, l1g + 2 * PD, l1b + 2 * PD, gt, th, tl);
    run_gemm(2, th, tl, w1h + 2 * DF, w1l + 2 * DF, b1 + 2 * PF, nullptr, hh, hl, PM, PF, PD);
    run_gemm(0, hh, hl, w2h + 2 * DF, w2l + 2 * DF, b2 + 2 * PD, ga, nullptr, nullptr, PM, PD, PF);
    add_ln_kernel<0><<<PM, 128>>>(gt, ga, l2g + 2 * PD, l2b + 2 * PD, out, nullptr, nullptr);
}